// round 3
// baseline (speedup 1.0000x reference)
#include <cuda_runtime.h>

#define HWN (512 * 1024)   // 2^19 pixels per batch image
#define NN  (8 * HWN)
#define SAME_RANGE 0.2f

// Scratch (allocation-free):
// g_acc[t] = (sum_c0, sum_c1, sum_c2, count), accumulated with one v4 RED.
// g_dlut[t] = min depth bits (depth in [0,1): uint order == float order).
// g_idx[i]  = target index of source pixel i (computed once in zmin).
__device__ float4 g_acc[NN];          // 64MB
__device__ unsigned int g_dlut[NN];   // 16MB
__device__ int g_idx[NN];             // 16MB

__device__ __forceinline__ void targets4(int i, const float* __restrict__ flow,
                                         int4& t) {
    int b = i >> 19;              // batch  (HWN = 2^19)
    int p = i & (HWN - 1);
    int y = p >> 10;              // W = 1024 = 2^10
    int x = p & 1023;
    const float* fb = flow + (size_t)b * 2 * HWN;
    float4 fx = *reinterpret_cast<const float4*>(fb + p);
    float4 fy = *reinterpret_cast<const float4*>(fb + HWN + p);
    float yf = (float)y;

    float px0 = fminf(fmaxf((float)(x + 0) + fx.x, 0.0f), 1023.0f);
    float px1 = fminf(fmaxf((float)(x + 1) + fx.y, 0.0f), 1023.0f);
    float px2 = fminf(fmaxf((float)(x + 2) + fx.z, 0.0f), 1023.0f);
    float px3 = fminf(fmaxf((float)(x + 3) + fx.w, 0.0f), 1023.0f);
    float py0 = fminf(fmaxf(yf + fy.x, 0.0f), 511.0f);
    float py1 = fminf(fmaxf(yf + fy.y, 0.0f), 511.0f);
    float py2 = fminf(fmaxf(yf + fy.z, 0.0f), 511.0f);
    float py3 = fminf(fmaxf(yf + fy.w, 0.0f), 511.0f);

    int base = b << 19;
    t.x = base + ((int)rintf(py0) << 10) + (int)rintf(px0);
    t.y = base + ((int)rintf(py1) << 10) + (int)rintf(px1);
    t.z = base + ((int)rintf(py2) << 10) + (int)rintf(px2);
    t.w = base + ((int)rintf(py3) << 10) + (int)rintf(px3);
}

// Pass 1: clear acc (owner stores, rides free under atomic-bound kernel),
// compute + store target indices, and atomicMin the z-buffer with
// adjacent-duplicate merging to cut REDG lanes.
__global__ void zmin_kernel(const float* __restrict__ flow,
                            const float* __restrict__ depth) {
    int i = (blockIdx.x * blockDim.x + threadIdx.x) << 2;

    // Clear this thread's own acc cells (no race: splat runs in a later kernel).
    float4 z = make_float4(0.0f, 0.0f, 0.0f, 0.0f);
    g_acc[i + 0] = z;
    g_acc[i + 1] = z;
    g_acc[i + 2] = z;
    g_acc[i + 3] = z;

    int4 t;
    targets4(i, flow, t);
    *reinterpret_cast<int4*>(&g_idx[i]) = t;

    float4 dv = *reinterpret_cast<const float4*>(depth + i);
    int ts[4] = {t.x, t.y, t.z, t.w};
    unsigned int ds[4] = {__float_as_uint(dv.x), __float_as_uint(dv.y),
                          __float_as_uint(dv.z), __float_as_uint(dv.w)};

    // Run-merge adjacent equal targets, then one atomicMin per run.
    int cur_t = ts[0];
    unsigned int cur_d = ds[0];
    #pragma unroll
    for (int k = 1; k < 4; k++) {
        if (ts[k] == cur_t) {
            cur_d = min(cur_d, ds[k]);
        } else {
            atomicMin(&g_dlut[cur_t], cur_d);
            cur_t = ts[k];
            cur_d = ds[k];
        }
    }
    atomicMin(&g_dlut[cur_t], cur_d);
}

__device__ __forceinline__ void red_add_v4(float4* p, float a, float b, float c, float d) {
    asm volatile("red.global.add.v4.f32 [%0], {%1, %2, %3, %4};"
                 :: "l"(p), "f"(a), "f"(b), "f"(c), "f"(d) : "memory");
}

// Pass 2: keep-test against z-buffer, splat (sum_c0..2, count) with one v4 RED
// per merged run of adjacent equal targets.
__global__ void splat_kernel(const float* __restrict__ obj,
                             const float* __restrict__ depth) {
    int i = (blockIdx.x * blockDim.x + threadIdx.x) << 2;
    int4 t = *reinterpret_cast<const int4*>(&g_idx[i]);
    float4 dv = *reinterpret_cast<const float4*>(depth + i);

    float m0 = __uint_as_float(g_dlut[t.x]) + SAME_RANGE;
    float m1 = __uint_as_float(g_dlut[t.y]) + SAME_RANGE;
    float m2 = __uint_as_float(g_dlut[t.z]) + SAME_RANGE;
    float m3 = __uint_as_float(g_dlut[t.w]) + SAME_RANGE;

    int b = i >> 19;
    int p = i & (HWN - 1);
    const float* ob = obj + (size_t)b * 3 * HWN;
    float4 o0 = *reinterpret_cast<const float4*>(ob + 0 * HWN + p);
    float4 o1 = *reinterpret_cast<const float4*>(ob + 1 * HWN + p);
    float4 o2 = *reinterpret_cast<const float4*>(ob + 2 * HWN + p);

    int ts[4]   = {t.x, t.y, t.z, t.w};
    bool keep[4] = {dv.x <= m0, dv.y <= m1, dv.z <= m2, dv.w <= m3};
    float c0s[4] = {o0.x, o0.y, o0.z, o0.w};
    float c1s[4] = {o1.x, o1.y, o1.z, o1.w};
    float c2s[4] = {o2.x, o2.y, o2.z, o2.w};

    int cur_t = ts[0];
    float a0 = keep[0] ? c0s[0] : 0.0f;
    float a1 = keep[0] ? c1s[0] : 0.0f;
    float a2 = keep[0] ? c2s[0] : 0.0f;
    float ac = keep[0] ? 1.0f : 0.0f;
    #pragma unroll
    for (int k = 1; k < 4; k++) {
        if (ts[k] == cur_t) {
            if (keep[k]) { a0 += c0s[k]; a1 += c1s[k]; a2 += c2s[k]; ac += 1.0f; }
        } else {
            if (ac > 0.0f) red_add_v4(&g_acc[cur_t], a0, a1, a2, ac);
            cur_t = ts[k];
            a0 = keep[k] ? c0s[k] : 0.0f;
            a1 = keep[k] ? c1s[k] : 0.0f;
            a2 = keep[k] ? c2s[k] : 0.0f;
            ac = keep[k] ? 1.0f : 0.0f;
        }
    }
    if (ac > 0.0f) red_add_v4(&g_acc[cur_t], a0, a1, a2, ac);
}

// Pass 3: out = sum / count (0 where count == 0). Writes every pixel, so no
// out memset is needed.
__global__ void normalize_kernel(float* __restrict__ out) {
    int i = (blockIdx.x * blockDim.x + threadIdx.x) << 2;
    int b = i >> 19;
    int p = i & (HWN - 1);

    float4 a0 = g_acc[i + 0];
    float4 a1 = g_acc[i + 1];
    float4 a2 = g_acc[i + 2];
    float4 a3 = g_acc[i + 3];

    float r0 = a0.w > 0.0f ? __fdividef(1.0f, a0.w) : 0.0f;
    float r1 = a1.w > 0.0f ? __fdividef(1.0f, a1.w) : 0.0f;
    float r2 = a2.w > 0.0f ? __fdividef(1.0f, a2.w) : 0.0f;
    float r3 = a3.w > 0.0f ? __fdividef(1.0f, a3.w) : 0.0f;

    float4 c0 = make_float4(a0.x * r0, a1.x * r1, a2.x * r2, a3.x * r3);
    float4 c1 = make_float4(a0.y * r0, a1.y * r1, a2.y * r2, a3.y * r3);
    float4 c2 = make_float4(a0.z * r0, a1.z * r1, a2.z * r2, a3.z * r3);

    float* outb = out + (size_t)b * 3 * HWN;
    *reinterpret_cast<float4*>(outb + 0 * HWN + p) = c0;
    *reinterpret_cast<float4*>(outb + 1 * HWN + p) = c1;
    *reinterpret_cast<float4*>(outb + 2 * HWN + p) = c2;
}

extern "C" void kernel_launch(void* const* d_in, const int* in_sizes, int n_in,
                              void* d_out, int out_size) {
    const float* obj   = (const float*)d_in[0];
    const float* flow  = (const float*)d_in[1];
    const float* depth = (const float*)d_in[2];
    float* out = (float*)d_out;

    void* dlut_ptr = nullptr;
    cudaGetSymbolAddress(&dlut_ptr, g_dlut);

    // dlut -> 0xFFFFFFFF (atomicMin identity; real depth bits < 0x3F800000).
    // acc is cleared inside zmin_kernel by owner threads.
    cudaMemsetAsync(dlut_ptr, 0xFF, (size_t)NN * sizeof(unsigned int), 0);

    const int TPB = 256;
    const int blocks = NN / 4 / TPB;  // exact: NN = 4M
    zmin_kernel<<<blocks, TPB, 0, 0>>>(flow, depth);
    splat_kernel<<<blocks, TPB, 0, 0>>>(obj, depth);
    normalize_kernel<<<blocks, TPB, 0, 0>>>(out);
}